// round 7
// baseline (speedup 1.0000x reference)
#include <cuda_runtime.h>
#include <cuda_fp16.h>
#include <math.h>
#include <stdint.h>

#define S_LEN 4096
#define B_DIM 32
#define H_DIM 512
#define NROW  (S_LEN * B_DIM)   // 131072

// ---------------- device scratch: fp16 hi/lo splits ----------------
__device__ __half g_Bh[H_DIM * H_DIM];     // Bt[n][k] = hi(W[k][n])
__device__ __half g_Bl[H_DIM * H_DIM];     // lo
__device__ __half g_Eh[(size_t)NROW * H_DIM];  // hi(enc), 128MB
__device__ __half g_El[(size_t)NROW * H_DIM];  // lo(enc), 128MB

__device__ __forceinline__ uint32_t smem_u32(const void* p) {
    uint32_t a;
    asm("{ .reg .u64 t; cvta.to.shared.u64 t, %1; cvt.u32.u64 %0, t; }" : "=r"(a) : "l"(p));
    return a;
}

#define LDSM4(r0, r1, r2, r3, addr) \
    asm volatile("ldmatrix.sync.aligned.m8n8.x4.shared.b16 {%0,%1,%2,%3}, [%4];" \
        : "=r"(r0), "=r"(r1), "=r"(r2), "=r"(r3) : "r"(addr))

#define MMA16816(c, a, b0, b1) \
    asm volatile("mma.sync.aligned.m16n8k16.row.col.f32.f16.f16.f32 " \
        "{%0,%1,%2,%3}, {%4,%5,%6,%7}, {%8,%9}, {%0,%1,%2,%3};" \
        : "+f"((c)[0]), "+f"((c)[1]), "+f"((c)[2]), "+f"((c)[3]) \
        : "r"((a)[0]), "r"((a)[1]), "r"((a)[2]), "r"((a)[3]), "r"(b0), "r"(b1))

#define CP16(dst, src) \
    asm volatile("cp.async.cg.shared.global [%0], [%1], 16;" :: "r"(dst), "l"(src))
#define CP_COMMIT() asm volatile("cp.async.commit_group;" ::: "memory")
#define CP_WAIT(n)  asm volatile("cp.async.wait_group %0;" :: "n"(n) : "memory")

__device__ __forceinline__ void split4(float4 v, uint2& hi, uint2& lo) {
    __half2 h01 = __floats2half2_rn(v.x, v.y);
    __half2 h23 = __floats2half2_rn(v.z, v.w);
    float2 f01 = __half22float2(h01);
    float2 f23 = __half22float2(h23);
    __half2 l01 = __floats2half2_rn(v.x - f01.x, v.y - f01.y);
    __half2 l23 = __floats2half2_rn(v.z - f23.x, v.w - f23.y);
    hi.x = *(uint32_t*)&h01; hi.y = *(uint32_t*)&h23;
    lo.x = *(uint32_t*)&l01; lo.y = *(uint32_t*)&l23;
}

// ---------------- kernel 0a: split W (transposed) ----------------
__global__ __launch_bounds__(256) void split_w(const float* __restrict__ Wm) {
    int idx = blockIdx.x * 256 + threadIdx.x;   // 0 .. 262143
    int k = idx >> 9, n = idx & 511;
    float v = Wm[idx];
    __half hi = __float2half_rn(v);
    g_Bh[n * H_DIM + k] = hi;
    g_Bl[n * H_DIM + k] = __float2half_rn(v - __half2float(hi));
}

// ---------------- kernel 0b: split enc (straight layout) ----------------
__global__ __launch_bounds__(256) void split_enc(const float4* __restrict__ enc4) {
    size_t f = blockIdx.x * 256 + threadIdx.x;
#pragma unroll
    for (int i = 0; i < 8; ++i, f += 8192 * 256) {
        float4 v = enc4[f];
        uint2 hi, lo; split4(v, hi, lo);
        *(uint2*)(g_Eh + 4 * f) = hi;
        *(uint2*)(g_El + 4 * f) = lo;
    }
}

// ---------------- kernel 1: 3xFP16 mma.sync GEMM-bilinear -> logits ----------
// rows r = s*32+b; A[m] = Enc[r-32] (rows r<32 garbage, fixed by kernel 2)
// logit[r] = sum_n C[r,n] * Enc[r,n] * hid[b,n]
//
// SMEM per buffer: 4 tiles (A_hi, A_lo, B_hi, B_lo), 128 rows x 40 halfs (80B)
#define TSTRIDE_B 80
#define TILE_B    (128 * TSTRIDE_B)   // 10240
#define BUF_B     (4 * TILE_B)        // 40960
#define SMEM_TOTAL (2 * BUF_B)        // 81920

__global__ __launch_bounds__(256, 2) void bilinear_hmma(
    const float* __restrict__ enc, const float* __restrict__ hid,
    float* __restrict__ logits)
{
    extern __shared__ char smem[];
    const uint32_t sb = smem_u32(smem);
    const int tid = threadIdx.x;
    const int lane = tid & 31, wid = tid >> 5;
    const int warp_m = wid >> 2;     // 0..1 : m offset 64*warp_m
    const int warp_n = wid & 3;      // 0..3 : n offset 32*warp_n
    const int m0 = blockIdx.x * 128;

    // ---- cp.async mapping: thread t -> tile rows (t>>2), (t>>2)+64; 16B chunk t&3
    const int crow = tid >> 2;            // 0..63
    const int cchk = (tid & 3) * 8;       // half offset within row (8 halfs/16B)
    long gr0 = (long)m0 + crow - B_DIM;      if (gr0 < 0) gr0 = 0;
    long gr1 = (long)m0 + crow + 64 - B_DIM; if (gr1 < 0) gr1 = 0;
    const size_t aoff0 = (size_t)gr0 * H_DIM + cchk;
    const size_t aoff1 = (size_t)gr1 * H_DIM + cchk;
    const size_t boff0 = (size_t)crow * H_DIM + cchk;
    const size_t boff1 = boff0 + (size_t)64 * H_DIM;
    const uint32_t dst0 = sb + (uint32_t)(crow * TSTRIDE_B + (tid & 3) * 16);
    const uint32_t dstR = 64 * TSTRIDE_B;

    // ---- ldmatrix addresses ----
    uint32_t a_addr[4];
#pragma unroll
    for (int mt = 0; mt < 4; ++mt)
        a_addr[mt] = sb + (uint32_t)((warp_m * 64 + mt * 16 + (lane & 15)) * TSTRIDE_B
                                     + ((lane >> 4) & 1) * 16);
    uint32_t b_addr[2];
#pragma unroll
    for (int p = 0; p < 2; ++p)
        b_addr[p] = sb + 2 * TILE_B + (uint32_t)((warp_n * 32 + p * 16 + (lane & 15)) * TSTRIDE_B
                                                 + ((lane >> 4) & 1) * 16);

    float rowacc[4][2];
#pragma unroll
    for (int mt = 0; mt < 4; ++mt) { rowacc[mt][0] = 0.f; rowacc[mt][1] = 0.f; }

#pragma unroll 1
    for (int nt = 0; nt < 4; ++nt) {
        const size_t nb = (size_t)nt * 128 * H_DIM;

        float cacc[4][4][4];
#pragma unroll
        for (int mt = 0; mt < 4; ++mt)
#pragma unroll
            for (int ntl = 0; ntl < 4; ++ntl)
#pragma unroll
                for (int q = 0; q < 4; ++q) cacc[mt][ntl][q] = 0.f;

        // stage issuer: 8 x 16B cp.async into buffer
        auto issue = [&](int stage) {
            const int kb = stage * 32;
            const uint32_t d = dst0 + (stage & 1) * (uint32_t)BUF_B;
            CP16(d,                           g_Eh + aoff0 + kb);
            CP16(d + dstR,                    g_Eh + aoff1 + kb);
            CP16(d + TILE_B,                  g_El + aoff0 + kb);
            CP16(d + TILE_B + dstR,           g_El + aoff1 + kb);
            CP16(d + 2 * TILE_B,              g_Bh + nb + boff0 + kb);
            CP16(d + 2 * TILE_B + dstR,       g_Bh + nb + boff1 + kb);
            CP16(d + 3 * TILE_B,              g_Bl + nb + boff0 + kb);
            CP16(d + 3 * TILE_B + dstR,       g_Bl + nb + boff1 + kb);
            CP_COMMIT();
        };

        issue(0);

#pragma unroll 1
        for (int st = 0; st < 16; ++st) {
            if (st < 15) { issue(st + 1); CP_WAIT(1); }
            else         { CP_WAIT(0); }
            __syncthreads();

            const uint32_t boffb = (st & 1) ? (uint32_t)BUF_B : 0u;
#pragma unroll
            for (int kk = 0; kk < 2; ++kk) {
                const uint32_t koff = boffb + kk * 32;
                uint32_t afh[4][4], afl[4][4];
                uint32_t bfh[4][2], bfl[4][2];
                // A_hi + B_hi
#pragma unroll
                for (int mt = 0; mt < 4; ++mt)
                    LDSM4(afh[mt][0], afh[mt][1], afh[mt][2], afh[mt][3], a_addr[mt] + koff);
#pragma unroll
                for (int p = 0; p < 2; ++p) {
                    uint32_t r0, r1, r2, r3;
                    LDSM4(r0, r1, r2, r3, b_addr[p] + koff);
                    bfh[2 * p][0] = r0;     bfh[2 * p][1] = r2;
                    bfh[2 * p + 1][0] = r1; bfh[2 * p + 1][1] = r3;
                }
                // hi * hi
#pragma unroll
                for (int mt = 0; mt < 4; ++mt)
#pragma unroll
                    for (int ntl = 0; ntl < 4; ++ntl)
                        MMA16816(cacc[mt][ntl], afh[mt], bfh[ntl][0], bfh[ntl][1]);
                // lo * hi (A_lo tile at +TILE_B)
#pragma unroll
                for (int mt = 0; mt < 4; ++mt)
                    LDSM4(afl[mt][0], afl[mt][1], afl[mt][2], afl[mt][3],
                          a_addr[mt] + koff + TILE_B);
#pragma unroll
                for (int mt = 0; mt < 4; ++mt)
#pragma unroll
                    for (int ntl = 0; ntl < 4; ++ntl)
                        MMA16816(cacc[mt][ntl], afl[mt], bfh[ntl][0], bfh[ntl][1]);
                // hi * lo (B_lo tile at +TILE_B from b_addr base)
#pragma unroll
                for (int p = 0; p < 2; ++p) {
                    uint32_t r0, r1, r2, r3;
                    LDSM4(r0, r1, r2, r3, b_addr[p] + koff + TILE_B);
                    bfl[2 * p][0] = r0;     bfl[2 * p][1] = r2;
                    bfl[2 * p + 1][0] = r1; bfl[2 * p + 1][1] = r3;
                }
#pragma unroll
                for (int mt = 0; mt < 4; ++mt)
#pragma unroll
                    for (int ntl = 0; ntl < 4; ++ntl)
                        MMA16816(cacc[mt][ntl], afh[mt], bfl[ntl][0], bfl[ntl][1]);
            }
            __syncthreads();
        }

        // ---- fused epilogue: rowacc += C .* (Enc .* hid), this n-tile ----
        const int nbase = nt * 128;
#pragma unroll
        for (int mt = 0; mt < 4; ++mt) {
#pragma unroll
            for (int j = 0; j < 2; ++j) {
                const int r = m0 + warp_m * 64 + mt * 16 + (lane >> 2) + j * 8;
                const float* er = enc + (size_t)r * H_DIM;
                const float* hr = hid + (size_t)(r & 31) * H_DIM;
                float acc = 0.f;
#pragma unroll
                for (int ntl = 0; ntl < 4; ++ntl) {
                    const int col = nbase + warp_n * 32 + ntl * 8 + (lane & 3) * 2;
                    const float2 e = *(const float2*)(er + col);
                    const float2 h = *(const float2*)(hr + col);
                    acc = fmaf(cacc[mt][ntl][j * 2 + 0], e.x * h.x, acc);
                    acc = fmaf(cacc[mt][ntl][j * 2 + 1], e.y * h.y, acc);
                }
                rowacc[mt][j] += acc;
            }
        }
    }

    // ---- reduce: quad lanes -> shared rows -> global ----
    __syncthreads();
    float* srow = (float*)smem;
    if (tid < 128) srow[tid] = 0.f;
    __syncthreads();
#pragma unroll
    for (int mt = 0; mt < 4; ++mt)
#pragma unroll
        for (int j = 0; j < 2; ++j) {
            float v = rowacc[mt][j];
            v += __shfl_xor_sync(0xffffffffu, v, 1);
            v += __shfl_xor_sync(0xffffffffu, v, 2);
            if ((lane & 3) == 0)
                atomicAdd(&srow[warp_m * 64 + mt * 16 + (lane >> 2) + j * 8], v);
        }
    __syncthreads();
    if (tid < 128) {
        const int r = m0 + tid;
        logits[(r & 31) * S_LEN + (r >> 5)] = srow[tid];   // out[b*4096 + s]
    }
}

// ---------------- kernel 2: affect term + s==0 fixup + softmax ----------------
__global__ __launch_bounds__(256) void softmax_finalize(
    const float* __restrict__ enc, const float* __restrict__ hid,
    const float* __restrict__ emb, const float* __restrict__ aff,
    float* __restrict__ out)
{
    const int b = blockIdx.x;
    const int tid = threadIdx.x;
    const int lane = tid & 31, wid = tid >> 5;
    __shared__ float red[8][4];
    __shared__ float fin[4];
    __shared__ float rmax[8];
    __shared__ float rsum[8];

    float a0 = 0.f, a1 = 0.f, a2 = 0.f, e0 = 0.f;
    for (int h = tid; h < H_DIM; h += 256) {
        const float hv = hid[b * H_DIM + h];
        a0 += hv * aff[h * 3 + 0];
        a1 += hv * aff[h * 3 + 1];
        a2 += hv * aff[h * 3 + 2];
        e0 += hv * enc[b * H_DIM + h];
    }
#pragma unroll
    for (int m = 16; m; m >>= 1) {
        a0 += __shfl_xor_sync(~0u, a0, m);
        a1 += __shfl_xor_sync(~0u, a1, m);
        a2 += __shfl_xor_sync(~0u, a2, m);
        e0 += __shfl_xor_sync(~0u, e0, m);
    }
    if (lane == 0) { red[wid][0] = a0; red[wid][1] = a1; red[wid][2] = a2; red[wid][3] = e0; }
    __syncthreads();
    if (tid < 4) {
        float s = 0.f;
        for (int w = 0; w < 8; ++w) s += red[w][tid];
        fin[tid] = s;
    }
    __syncthreads();
    const float A0 = fin[0], A1 = fin[1], A2 = fin[2], E0 = fin[3];

    float l[16];
    float mx = -INFINITY;
#pragma unroll
    for (int it = 0; it < 16; ++it) {
        const int s = tid + it * 256;
        float v = (s == 0) ? E0 : out[b * S_LEN + s];
        const float* ep = emb + ((size_t)s * B_DIM + b) * 3;
        v += A0 * ep[0] + A1 * ep[1] + A2 * ep[2];
        l[it] = v;
        mx = fmaxf(mx, v);
    }
#pragma unroll
    for (int m = 16; m; m >>= 1) mx = fmaxf(mx, __shfl_xor_sync(~0u, mx, m));
    if (lane == 0) rmax[wid] = mx;
    __syncthreads();
    if (tid == 0) {
        float m2 = rmax[0];
        for (int w = 1; w < 8; ++w) m2 = fmaxf(m2, rmax[w]);
        rmax[0] = m2;
    }
    __syncthreads();
    const float MX = rmax[0];

    float sum = 0.f;
#pragma unroll
    for (int it = 0; it < 16; ++it) { l[it] = expf(l[it] - MX); sum += l[it]; }
#pragma unroll
    for (int m = 16; m; m >>= 1) sum += __shfl_xor_sync(~0u, sum, m);
    if (lane == 0) rsum[wid] = sum;
    __syncthreads();
    if (tid == 0) {
        float s2 = 0.f;
        for (int w = 0; w < 8; ++w) s2 += rsum[w];
        rsum[0] = s2;
    }
    __syncthreads();
    const float inv = 1.0f / rsum[0];
#pragma unroll
    for (int it = 0; it < 16; ++it)
        out[b * S_LEN + tid + it * 256] = l[it] * inv;
}

// ---------------- launch ----------------
extern "C" void kernel_launch(void* const* d_in, const int* in_sizes, int n_in,
                              void* d_out, int out_size) {
    const float *hid = nullptr, *enc = nullptr, *emb = nullptr, *Wm = nullptr, *aff = nullptr;
    for (int i = 0; i < n_in; ++i) {
        switch (in_sizes[i]) {
            case 16384:    hid = (const float*)d_in[i]; break;  // hidden [1,32,512]
            case 67108864: enc = (const float*)d_in[i]; break;  // encoder_outputs [4096,32,512]
            case 393216:   emb = (const float*)d_in[i]; break;  // embedding [4096,32,3]
            case 262144:   Wm  = (const float*)d_in[i]; break;  // bigram_matrix [512,512]
            case 1536:     aff = (const float*)d_in[i]; break;  // affect_matrix [512,3]
        }
    }
    float* out = (float*)d_out;  // [32,1,4096] fp32; logits scratch then softmax

    cudaFuncSetAttribute(bilinear_hmma,
                         cudaFuncAttributeMaxDynamicSharedMemorySize, SMEM_TOTAL);

    split_w<<<(H_DIM * H_DIM) / 256, 256>>>(Wm);
    split_enc<<<8192, 256>>>((const float4*)enc);
    bilinear_hmma<<<(S_LEN * B_DIM) / 128, 256, SMEM_TOTAL>>>(enc, hid, out);
    softmax_finalize<<<B_DIM, 256>>>(enc, hid, emb, aff, out);
}